// round 1
// baseline (speedup 1.0000x reference)
#include <cuda_runtime.h>
#include <math_constants.h>

// ---------------------------------------------------------------------------
// DIMES dense encoder, B=16, N=200, U=64, L=3
// Layout: w[b][n][m][u] edge tensor (163MB), z scratch (163MB)
// ---------------------------------------------------------------------------

constexpr int B_ = 16, N_ = 200, M_ = 199, U_ = 64, L_ = 3;
constexpr int BN_ = B_ * N_;                     // 3200
constexpr long long E_ = (long long)BN_ * M_;    // 636800 edge rows
constexpr float EPS_ = 1e-5f;

__device__ __align__(16) float g_w[(size_t)636800 * 64];
__device__ __align__(16) float g_z[(size_t)636800 * 64];
__device__ __align__(16) float g_h[BN_ * U_];
__device__ __align__(16) float g_x1[BN_ * U_];
__device__ __align__(16) float g_x2[BN_ * U_];
__device__ __align__(16) float g_x3[BN_ * U_];
__device__ __align__(16) float g_x4[BN_ * U_];
__device__ __align__(16) float g_pooled[BN_ * U_];
__device__ double g_estats[2 * U_];   // sum, sumsq over edges (per u)
__device__ double g_hstats[2 * U_];   // sum, sumsq over (B,N)  (per u)
__device__ __align__(16) float g_ecoef[2 * U_];  // scale, shift
__device__ __align__(16) float g_hcoef[2 * U_];

__device__ __forceinline__ float lrelu(float v) { return v >= 0.f ? v : 0.01f * v; }

// h = lrelu(x @ v_lin0_w + b)
__global__ void k_init_h(const float* __restrict__ x,
                         const float* __restrict__ w0,
                         const float* __restrict__ b0) {
    int idx = blockIdx.x * 256 + threadIdx.x;
    if (idx >= BN_ * U_) return;
    int row = idx >> 6, u = idx & 63;
    float v = x[row * 2] * w0[u] + x[row * 2 + 1] * w0[U_ + u] + b0[u];
    g_h[idx] = lrelu(v);
}

// w[b,n,m,u] = lrelu(adj[b,n,dst] * ew0[u] + eb0[u]),  dst = m + (m>=n)
__global__ void k_init_w(const float* __restrict__ adj,
                         const float* __restrict__ ew0,
                         const float* __restrict__ eb0) {
    int n = blockIdx.y, b = blockIdx.z;
    int t = threadIdx.x;
    int m = blockIdx.x * 4 + (t >> 6);
    int u = t & 63;
    if (m >= M_) return;
    int dst = m + (m >= n);
    float a = __ldg(&adj[((size_t)(b * N_ + n)) * N_ + dst]);
    size_t o = ((size_t)(b * N_ + n) * M_ + m) * U_ + u;
    g_w[o] = lrelu(a * ew0[u] + eb0[u]);
}

// x1..x4 = h @ v_wK + v_bK   (one block per (b,n); 4 mats x 64 cols = 256 thr)
__global__ void k_xs(const float* __restrict__ w1, const float* __restrict__ b1,
                     const float* __restrict__ w2, const float* __restrict__ b2,
                     const float* __restrict__ w3, const float* __restrict__ b3,
                     const float* __restrict__ w4, const float* __restrict__ b4) {
    __shared__ float hsh[U_];
    int bn = blockIdx.x, t = threadIdx.x;
    if (t < U_) hsh[t] = g_h[bn * U_ + t];
    __syncthreads();
    int mat = t >> 6, col = t & 63;
    const float* W; const float* bb; float* out;
    switch (mat) {
        case 0:  W = w1; bb = b1; out = g_x1; break;
        case 1:  W = w2; bb = b2; out = g_x2; break;
        case 2:  W = w3; bb = b3; out = g_x3; break;
        default: W = w4; bb = b4; out = g_x4; break;
    }
    float acc = __ldg(&bb[col]);
#pragma unroll
    for (int k = 0; k < U_; k++) acc = fmaf(hsh[k], __ldg(&W[k * U_ + col]), acc);
    out[bn * U_ + col] = acc;
}

// Fused big pass 1 (per layer): one block per (b,n).
//  - z = w @ Ew + Eb + x3[b,n] + x4[b,dst]   -> written to g_z
//  - pooled[u] = max_m sigmoid(w) * x2[b,dst]
//  - BN stats (edges -> g_estats, h pre-act -> g_hstats) via atomics
__global__ void __launch_bounds__(256) k_pass1(const float* __restrict__ Ew,
                                               const float* __restrict__ Eb) {
    __shared__ float4 Ewt[U_][17];      // Ew^T, padded row (68 floats) for bank-safety
    __shared__ float w_sh[16][U_];
    __shared__ float red[4][U_];
    int bn = blockIdx.x;
    int n = bn % N_;
    int b = bn / N_;
    int t = threadIdx.x, u = t & 63, g = t >> 6;

    // Load Ew transposed: Ewt[u][k] = Ew[k][u]
    for (int idx = t; idx < U_ * U_; idx += 256) {
        int uu = idx & 63, kk = idx >> 6;
        ((float*)Ewt)[uu * 68 + kk] = __ldg(&Ew[kk * U_ + uu]);
    }
    float zc = __ldg(&Eb[u]) + g_x3[bn * U_ + u];
    const float* x2b = g_x2 + (size_t)b * N_ * U_;
    const float* x4b = g_x4 + (size_t)b * N_ * U_;
    const float* wbase = g_w + (size_t)bn * M_ * U_;
    float* zbase = g_z + (size_t)bn * M_ * U_;

    float esum = 0.f, esq = 0.f, pooled = -CUDART_INF_F;

    for (int m0 = 0; m0 < M_; m0 += 16) {
        int rows = min(16, M_ - m0);
        __syncthreads();
        for (int idx = t; idx < 16 * U_; idx += 256) {
            int r = idx >> 6, c = idx & 63;
            w_sh[r][c] = (r < rows) ? wbase[(size_t)(m0 + r) * U_ + c] : 0.f;
        }
        __syncthreads();

        // GEMV tile: thread computes z for rows {g, 4+g, 8+g, 12+g}, column u
        float acc[4] = {0.f, 0.f, 0.f, 0.f};
#pragma unroll
        for (int k4 = 0; k4 < 16; k4++) {
            float4 e4 = Ewt[u][k4];
#pragma unroll
            for (int j = 0; j < 4; j++) {
                const float4 w4 = *reinterpret_cast<const float4*>(&w_sh[4 * j + g][k4 * 4]);
                acc[j] += w4.x * e4.x + w4.y * e4.y + w4.z * e4.z + w4.w * e4.w;
            }
        }
#pragma unroll
        for (int j = 0; j < 4; j++) {
            int r = 4 * j + g;
            if (r < rows) {
                int m = m0 + r;
                int dst = m + (m >= n);
                float x2v = __ldg(&x2b[dst * U_ + u]);
                float x4v = __ldg(&x4b[dst * U_ + u]);
                float wv = w_sh[r][u];
                float sg = 1.f / (1.f + __expf(-wv));
                pooled = fmaxf(pooled, sg * x2v);
                float z = acc[j] + zc + x4v;
                zbase[(size_t)m * U_ + u] = z;
                esum += z;
                esq = fmaf(z, z, esq);
            }
        }
    }

    // pooled reduction + h BN stats
    __syncthreads();
    red[g][u] = pooled;
    __syncthreads();
    if (g == 0) {
        float p = fmaxf(fmaxf(red[0][u], red[1][u]), fmaxf(red[2][u], red[3][u]));
        g_pooled[bn * U_ + u] = p;
        float zh = g_x1[bn * U_ + u] + p;
        atomicAdd(&g_hstats[u], (double)zh);
        atomicAdd(&g_hstats[U_ + u], (double)(zh * zh));
    }
    // edge BN stats
    __syncthreads();
    red[g][u] = esum;
    __syncthreads();
    if (g == 0) atomicAdd(&g_estats[u], (double)(red[0][u] + red[1][u] + red[2][u] + red[3][u]));
    __syncthreads();
    red[g][u] = esq;
    __syncthreads();
    if (g == 0) atomicAdd(&g_estats[U_ + u], (double)(red[0][u] + red[1][u] + red[2][u] + red[3][u]));
}

// Turn accumulated sums into BN scale/shift; reset accumulators.
__global__ void k_finalize(const float* __restrict__ hg, const float* __restrict__ hb,
                           const float* __restrict__ eg, const float* __restrict__ eb) {
    int u = threadIdx.x;  // 64 threads
    double ecnt = (double)E_;
    float emean = (float)(g_estats[u] / ecnt);
    float evar  = (float)(g_estats[U_ + u] / ecnt) - emean * emean;
    float es = eg[u] * rsqrtf(evar + EPS_);
    g_ecoef[u] = es;
    g_ecoef[U_ + u] = eb[u] - emean * es;

    double hcnt = (double)BN_;
    float hmean = (float)(g_hstats[u] / hcnt);
    float hvar  = (float)(g_hstats[U_ + u] / hcnt) - hmean * hmean;
    float hs = hg[u] * rsqrtf(hvar + EPS_);
    g_hcoef[u] = hs;
    g_hcoef[U_ + u] = hb[u] - hmean * hs;

    g_estats[u] = 0.0; g_estats[U_ + u] = 0.0;
    g_hstats[u] = 0.0; g_hstats[U_ + u] = 0.0;
}

// h += lrelu(bn(x1 + pooled))
__global__ void k_happly() {
    int idx = blockIdx.x * 256 + threadIdx.x;
    if (idx >= BN_ * U_) return;
    int u = idx & 63;
    float zh = g_x1[idx] + g_pooled[idx];
    g_h[idx] += lrelu(fmaf(zh, g_hcoef[u], g_hcoef[U_ + u]));
}

// w += lrelu(bn(z))   (pure streaming, float4)
__global__ void k_pass2() {
    size_t idx = (size_t)blockIdx.x * 256 + threadIdx.x;  // over E*16 float4s
    int u4 = (int)(idx & 15);
    float4 z = reinterpret_cast<const float4*>(g_z)[idx];
    float4 w = reinterpret_cast<float4*>(g_w)[idx];
    float4 s  = reinterpret_cast<const float4*>(g_ecoef)[u4];
    float4 sh = reinterpret_cast<const float4*>(g_ecoef)[16 + u4];
    w.x += lrelu(fmaf(z.x, s.x, sh.x));
    w.y += lrelu(fmaf(z.y, s.y, sh.y));
    w.z += lrelu(fmaf(z.z, s.z, sh.z));
    w.w += lrelu(fmaf(z.w, s.w, sh.w));
    reinterpret_cast<float4*>(g_w)[idx] = w;
}

// Last layer: fuse residual update with final projection w_new @ e_lin1_w.
// One block = 4 edge rows x 64 u-threads.
__global__ void __launch_bounds__(256) k_pass2_last(const float* __restrict__ e1w,
                                                    const float* __restrict__ e1b,
                                                    float* __restrict__ out) {
    __shared__ float sred[4][2];
    int t = threadIdx.x, u = t & 63, g = t >> 6;
    size_t e = (size_t)blockIdx.x * 4 + g;   // grid is exactly E_/4
    size_t o = e * U_ + u;
    float z = g_z[o], w = g_w[o];
    float wn = w + lrelu(fmaf(z, g_ecoef[u], g_ecoef[U_ + u]));
    float v = wn * __ldg(&e1w[u]);
#pragma unroll
    for (int off = 16; off; off >>= 1) v += __shfl_down_sync(0xffffffffu, v, off);
    int warp = t >> 5, lane = t & 31;
    if (lane == 0) sred[warp >> 1][warp & 1] = v;
    __syncthreads();
    if (u == 0) {
        float tot = sred[g][0] + sred[g][1] + __ldg(&e1b[0]);
        int ei = (int)e;
        int b = ei / (N_ * M_);
        int rem = ei - b * (N_ * M_);
        int n = rem / M_;
        int m = rem - n * M_;
        int dst = m + (m >= n);
        out[((size_t)(b * N_ + n)) * N_ + dst] = tot;
    }
}

__global__ void k_zdiag(float* __restrict__ out) {
    int idx = blockIdx.x * 256 + threadIdx.x;
    if (idx >= BN_) return;
    int b = idx / N_, n = idx % N_;
    out[((size_t)(b * N_ + n)) * N_ + n] = 0.f;
}

extern "C" void kernel_launch(void* const* d_in, const int* in_sizes, int n_in,
                              void* d_out, int out_size) {
    const float* x    = (const float*)d_in[0];
    const float* adj  = (const float*)d_in[1];
    const float* vl0w = (const float*)d_in[2];
    const float* vl0b = (const float*)d_in[3];
    const float* vw1  = (const float*)d_in[4];
    const float* vb1  = (const float*)d_in[5];
    const float* vw2  = (const float*)d_in[6];
    const float* vb2  = (const float*)d_in[7];
    const float* vw3  = (const float*)d_in[8];
    const float* vb3  = (const float*)d_in[9];
    const float* vw4  = (const float*)d_in[10];
    const float* vb4  = (const float*)d_in[11];
    const float* vbng = (const float*)d_in[12];
    const float* vbnb = (const float*)d_in[13];
    const float* el0w = (const float*)d_in[14];
    const float* el0b = (const float*)d_in[15];
    const float* ew   = (const float*)d_in[16];
    const float* eb   = (const float*)d_in[17];
    const float* ebng = (const float*)d_in[18];
    const float* ebnb = (const float*)d_in[19];
    const float* e1w  = (const float*)d_in[20];
    const float* e1b  = (const float*)d_in[21];
    float* out = (float*)d_out;

    k_init_h<<<(BN_ * U_ + 255) / 256, 256>>>(x, vl0w, vl0b);
    k_init_w<<<dim3(50, N_, B_), 256>>>(adj, el0w, el0b);

    for (int i = 0; i < L_; i++) {
        k_xs<<<BN_, 256>>>(vw1 + i * U_ * U_, vb1 + i * U_,
                           vw2 + i * U_ * U_, vb2 + i * U_,
                           vw3 + i * U_ * U_, vb3 + i * U_,
                           vw4 + i * U_ * U_, vb4 + i * U_);
        k_pass1<<<BN_, 256>>>(ew + i * U_ * U_, eb + i * U_);
        k_finalize<<<1, 64>>>(vbng + i * U_, vbnb + i * U_, ebng + i * U_, ebnb + i * U_);
        if (i < L_ - 1) {
            k_happly<<<(BN_ * U_ + 255) / 256, 256>>>();
            k_pass2<<<(int)(E_ * 16 / 256), 256>>>();
        } else {
            // h is not consumed after the last layer; skip k_happly.
            k_pass2_last<<<(int)(E_ / 4), 256>>>(e1w, e1b, out);
            k_zdiag<<<(BN_ + 255) / 256, 256>>>(out);
        }
    }
}

// round 2
// speedup vs baseline: 1.5731x; 1.5731x over previous
#include <cuda_runtime.h>
#include <math_constants.h>

// ---------------------------------------------------------------------------
// DIMES dense encoder, B=16, N=200, U=64, L=3
// w[b][n][m][u] edge tensor (163MB) + z scratch (163MB).
// Per layer one fused kernel: (apply prev BN residual) -> GEMM (tf32 mma.sync)
// -> sigmoid-pool -> z write -> BN stats.
// ---------------------------------------------------------------------------

constexpr int B_ = 16, N_ = 200, M_ = 199, U_ = 64, L_ = 3;
constexpr int BN_ = B_ * N_;                     // 3200
constexpr long long E_ = (long long)BN_ * M_;    // 636800 edge rows
constexpr float EPS_ = 1e-5f;

__device__ __align__(16) float g_w[(size_t)636800 * 64];
__device__ __align__(16) float g_z[(size_t)636800 * 64];
__device__ __align__(16) float g_h[BN_ * U_];
__device__ __align__(16) float g_x1[BN_ * U_];
__device__ __align__(16) float g_x2[BN_ * U_];
__device__ __align__(16) float g_x3[BN_ * U_];
__device__ __align__(16) float g_x4[BN_ * U_];
__device__ __align__(16) float g_pooled[BN_ * U_];
__device__ double g_estats[2 * U_];
__device__ double g_hstats[2 * U_];
__device__ __align__(16) float g_ecoef[2 * U_];  // scale, shift
__device__ __align__(16) float g_hcoef[2 * U_];

__device__ __forceinline__ float lrelu(float v) { return v >= 0.f ? v : 0.01f * v; }

__device__ __forceinline__ unsigned to_tf32(float f) {
    unsigned r;
    asm("cvt.rna.tf32.f32 %0, %1;" : "=r"(r) : "f"(f));
    return r;
}

__device__ __forceinline__ void mma_tf32(float c[4], unsigned a0, unsigned a1,
                                         unsigned a2, unsigned a3,
                                         unsigned b0, unsigned b1) {
    asm volatile(
        "mma.sync.aligned.m16n8k8.row.col.f32.tf32.tf32.f32 "
        "{%0,%1,%2,%3}, {%4,%5,%6,%7}, {%8,%9}, {%0,%1,%2,%3};"
        : "+f"(c[0]), "+f"(c[1]), "+f"(c[2]), "+f"(c[3])
        : "r"(a0), "r"(a1), "r"(a2), "r"(a3), "r"(b0), "r"(b1));
}

// h = lrelu(x @ v_lin0_w + b)
__global__ void k_init_h(const float* __restrict__ x,
                         const float* __restrict__ w0,
                         const float* __restrict__ b0) {
    int idx = blockIdx.x * 256 + threadIdx.x;
    if (idx >= BN_ * U_) return;
    int row = idx >> 6, u = idx & 63;
    float v = x[row * 2] * w0[u] + x[row * 2 + 1] * w0[U_ + u] + b0[u];
    g_h[idx] = lrelu(v);
}

// w[b,n,m,u] = lrelu(adj[b,n,dst] * ew0[u] + eb0[u]),  dst = m + (m>=n)
__global__ void k_init_w(const float* __restrict__ adj,
                         const float* __restrict__ ew0,
                         const float* __restrict__ eb0) {
    int n = blockIdx.y, b = blockIdx.z;
    int t = threadIdx.x;
    int m = blockIdx.x * 4 + (t >> 6);
    int u = t & 63;
    if (m >= M_) return;
    int dst = m + (m >= n);
    float a = __ldg(&adj[((size_t)(b * N_ + n)) * N_ + dst]);
    size_t o = ((size_t)(b * N_ + n) * M_ + m) * U_ + u;
    g_w[o] = lrelu(a * ew0[u] + eb0[u]);
}

// x1..x4 = h @ v_wK + v_bK
__global__ void k_xs(const float* __restrict__ w1, const float* __restrict__ b1,
                     const float* __restrict__ w2, const float* __restrict__ b2,
                     const float* __restrict__ w3, const float* __restrict__ b3,
                     const float* __restrict__ w4, const float* __restrict__ b4) {
    __shared__ float hsh[U_];
    int bn = blockIdx.x, t = threadIdx.x;
    if (t < U_) hsh[t] = g_h[bn * U_ + t];
    __syncthreads();
    int mat = t >> 6, col = t & 63;
    const float* W; const float* bb; float* out;
    switch (mat) {
        case 0:  W = w1; bb = b1; out = g_x1; break;
        case 1:  W = w2; bb = b2; out = g_x2; break;
        case 2:  W = w3; bb = b3; out = g_x3; break;
        default: W = w4; bb = b4; out = g_x4; break;
    }
    float acc = __ldg(&bb[col]);
#pragma unroll
    for (int k = 0; k < U_; k++) acc = fmaf(hsh[k], __ldg(&W[k * U_ + col]), acc);
    out[bn * U_ + col] = acc;
}

// ---------------------------------------------------------------------------
// Fused per-layer pass: one block per (b,n). 256 threads = 8 warps.
// Warp wp: m-tile mt=wp&3 (16 rows), n-half nh=wp>>2 (32 cols).
// Elementwise mapping: thread (r=t>>4, c=t&15): rows 4r+j, cols 4c..4c+3.
// ---------------------------------------------------------------------------
__global__ void __launch_bounds__(256) k_pass1(const float* __restrict__ Ew,
                                               const float* __restrict__ Eb,
                                               int apply_bn) {
    __shared__ float w_sh[64 * 68];   // tf32 w tile; reused as z staging
    __shared__ float e_sh[64 * 72];   // tf32 Ew, stride 72 (conflict-free B frags)
    __shared__ float red_sh[16 * 68];

    const int bn = blockIdx.x;
    const int n = bn % N_;
    const int b = bn / N_;
    const int t = threadIdx.x;
    const int c = t & 15, r = t >> 4;
    const int c4 = c * 4;
    const int lane = t & 31, wp = t >> 5;
    const int grp = lane >> 2, tig = lane & 3;
    const int mrow = (wp & 3) * 16 + grp;
    const int ncol0 = (wp >> 2) * 32;

    // Ew -> e_sh (tf32)
    for (int idx = t; idx < 1024; idx += 256) {
        int k = idx >> 4, q = (idx & 15) * 4;
        float4 v = __ldg((const float4*)&Ew[k * 64 + q]);
        v.x = __uint_as_float(to_tf32(v.x));
        v.y = __uint_as_float(to_tf32(v.y));
        v.z = __uint_as_float(to_tf32(v.z));
        v.w = __uint_as_float(to_tf32(v.w));
        *(float4*)&e_sh[k * 72 + q] = v;
    }

    float4 zc;
    {
        float4 e = __ldg((const float4*)&Eb[c4]);
        float4 x3v = *(const float4*)&g_x3[bn * U_ + c4];
        zc = make_float4(e.x + x3v.x, e.y + x3v.y, e.z + x3v.z, e.w + x3v.w);
    }

    float* wbase = g_w + (size_t)bn * M_ * U_;
    float* zbase = g_z + (size_t)bn * M_ * U_;
    const float* x2b = g_x2 + (size_t)b * N_ * U_;
    const float* x4b = g_x4 + (size_t)b * N_ * U_;

    float4 pool = make_float4(-CUDART_INF_F, -CUDART_INF_F, -CUDART_INF_F, -CUDART_INF_F);
    float4 esum = make_float4(0.f, 0.f, 0.f, 0.f);
    float4 esq  = make_float4(0.f, 0.f, 0.f, 0.f);

    for (int m0 = 0; m0 < M_; m0 += 64) {
        const int rows = min(64, M_ - m0);
        __syncthreads();
        // Load w tile; fuse previous layer's residual BN update; stash tf32 copy.
        for (int idx = t; idx < 1024; idx += 256) {
            int rr = idx >> 4, q = (idx & 15) * 4;
            float4 wv = make_float4(0.f, 0.f, 0.f, 0.f);
            if (rr < rows) {
                size_t go = (size_t)(m0 + rr) * U_ + q;
                wv = *(const float4*)&wbase[go];
                if (apply_bn) {
                    float4 zv = *(const float4*)&zbase[go];
                    float4 s  = *(const float4*)&g_ecoef[q];
                    float4 sh = *(const float4*)&g_ecoef[U_ + q];
                    wv.x += lrelu(fmaf(zv.x, s.x, sh.x));
                    wv.y += lrelu(fmaf(zv.y, s.y, sh.y));
                    wv.z += lrelu(fmaf(zv.z, s.z, sh.z));
                    wv.w += lrelu(fmaf(zv.w, s.w, sh.w));
                    *(float4*)&wbase[go] = wv;
                }
            }
            float4 wt;
            wt.x = __uint_as_float(to_tf32(wv.x));
            wt.y = __uint_as_float(to_tf32(wv.y));
            wt.z = __uint_as_float(to_tf32(wv.z));
            wt.w = __uint_as_float(to_tf32(wv.w));
            *(float4*)&w_sh[rr * 68 + q] = wt;
        }
        __syncthreads();

        // pooled partial: max_m sigmoid(w) * x2[dst]
#pragma unroll
        for (int j = 0; j < 4; j++) {
            int rr = 4 * r + j, m = m0 + rr;
            if (rr < rows) {
                int dst = m + (m >= n);
                float4 x2v = __ldg((const float4*)&x2b[dst * U_ + c4]);
                float4 wv = *(const float4*)&w_sh[rr * 68 + c4];
                pool.x = fmaxf(pool.x, x2v.x / (1.f + __expf(-wv.x)));
                pool.y = fmaxf(pool.y, x2v.y / (1.f + __expf(-wv.y)));
                pool.z = fmaxf(pool.z, x2v.z / (1.f + __expf(-wv.z)));
                pool.w = fmaxf(pool.w, x2v.w / (1.f + __expf(-wv.w)));
            }
        }

        // GEMM: z_tile = w_tile @ Ew  (tf32 tensor cores)
        float cf[4][4];
#pragma unroll
        for (int nt = 0; nt < 4; nt++) {
            cf[nt][0] = 0.f; cf[nt][1] = 0.f; cf[nt][2] = 0.f; cf[nt][3] = 0.f;
        }
#pragma unroll
        for (int k0 = 0; k0 < 64; k0 += 8) {
            unsigned a0 = __float_as_uint(w_sh[mrow * 68 + k0 + tig]);
            unsigned a1 = __float_as_uint(w_sh[(mrow + 8) * 68 + k0 + tig]);
            unsigned a2 = __float_as_uint(w_sh[mrow * 68 + k0 + tig + 4]);
            unsigned a3 = __float_as_uint(w_sh[(mrow + 8) * 68 + k0 + tig + 4]);
#pragma unroll
            for (int nt = 0; nt < 4; nt++) {
                int col = ncol0 + nt * 8 + grp;
                unsigned b0 = __float_as_uint(e_sh[(k0 + tig) * 72 + col]);
                unsigned b1 = __float_as_uint(e_sh[(k0 + tig + 4) * 72 + col]);
                mma_tf32(cf[nt], a0, a1, a2, a3, b0, b1);
            }
        }
        __syncthreads();   // all reads of w_sh done

        // stage z fragments into w_sh
#pragma unroll
        for (int nt = 0; nt < 4; nt++) {
            int cc = ncol0 + nt * 8 + 2 * tig;
            *(float2*)&w_sh[mrow * 68 + cc] = make_float2(cf[nt][0], cf[nt][1]);
            *(float2*)&w_sh[(mrow + 8) * 68 + cc] = make_float2(cf[nt][2], cf[nt][3]);
        }
        __syncthreads();

        // epilogue: z += zc + x4[dst]; write; BN stats
#pragma unroll
        for (int j = 0; j < 4; j++) {
            int rr = 4 * r + j, m = m0 + rr;
            if (rr < rows) {
                int dst = m + (m >= n);
                float4 x4v = __ldg((const float4*)&x4b[dst * U_ + c4]);
                float4 z4 = *(const float4*)&w_sh[rr * 68 + c4];
                z4.x += zc.x + x4v.x;
                z4.y += zc.y + x4v.y;
                z4.z += zc.z + x4v.z;
                z4.w += zc.w + x4v.w;
                *(float4*)&zbase[(size_t)m * U_ + c4] = z4;
                esum.x += z4.x; esq.x = fmaf(z4.x, z4.x, esq.x);
                esum.y += z4.y; esq.y = fmaf(z4.y, z4.y, esq.y);
                esum.z += z4.z; esq.z = fmaf(z4.z, z4.z, esq.z);
                esum.w += z4.w; esq.w = fmaf(z4.w, z4.w, esq.w);
            }
        }
    }

    // ---- block reductions over the 16 r-groups ----
    // pooled (max)
    __syncthreads();
    *(float4*)&red_sh[r * 68 + c4] = pool;
    __syncthreads();
#pragma unroll
    for (int s = 8; s >= 1; s >>= 1) {
        if (r < s) {
            float4 a = *(float4*)&red_sh[r * 68 + c4];
            float4 bb = *(float4*)&red_sh[(r + s) * 68 + c4];
            a.x = fmaxf(a.x, bb.x); a.y = fmaxf(a.y, bb.y);
            a.z = fmaxf(a.z, bb.z); a.w = fmaxf(a.w, bb.w);
            *(float4*)&red_sh[r * 68 + c4] = a;
        }
        __syncthreads();
    }
    if (r == 0) {
        float4 p = *(float4*)&red_sh[c4];
        *(float4*)&g_pooled[bn * U_ + c4] = p;
        float4 x1v = *(const float4*)&g_x1[bn * U_ + c4];
        float zh;
        zh = x1v.x + p.x; atomicAdd(&g_hstats[c4 + 0], (double)zh); atomicAdd(&g_hstats[U_ + c4 + 0], (double)(zh * zh));
        zh = x1v.y + p.y; atomicAdd(&g_hstats[c4 + 1], (double)zh); atomicAdd(&g_hstats[U_ + c4 + 1], (double)(zh * zh));
        zh = x1v.z + p.z; atomicAdd(&g_hstats[c4 + 2], (double)zh); atomicAdd(&g_hstats[U_ + c4 + 2], (double)(zh * zh));
        zh = x1v.w + p.w; atomicAdd(&g_hstats[c4 + 3], (double)zh); atomicAdd(&g_hstats[U_ + c4 + 3], (double)(zh * zh));
    }
    // esum
    __syncthreads();
    *(float4*)&red_sh[r * 68 + c4] = esum;
    __syncthreads();
#pragma unroll
    for (int s = 8; s >= 1; s >>= 1) {
        if (r < s) {
            float4 a = *(float4*)&red_sh[r * 68 + c4];
            float4 bb = *(float4*)&red_sh[(r + s) * 68 + c4];
            a.x += bb.x; a.y += bb.y; a.z += bb.z; a.w += bb.w;
            *(float4*)&red_sh[r * 68 + c4] = a;
        }
        __syncthreads();
    }
    if (r == 0) {
        float4 sv = *(float4*)&red_sh[c4];
        atomicAdd(&g_estats[c4 + 0], (double)sv.x);
        atomicAdd(&g_estats[c4 + 1], (double)sv.y);
        atomicAdd(&g_estats[c4 + 2], (double)sv.z);
        atomicAdd(&g_estats[c4 + 3], (double)sv.w);
    }
    // esq
    __syncthreads();
    *(float4*)&red_sh[r * 68 + c4] = esq;
    __syncthreads();
#pragma unroll
    for (int s = 8; s >= 1; s >>= 1) {
        if (r < s) {
            float4 a = *(float4*)&red_sh[r * 68 + c4];
            float4 bb = *(float4*)&red_sh[(r + s) * 68 + c4];
            a.x += bb.x; a.y += bb.y; a.z += bb.z; a.w += bb.w;
            *(float4*)&red_sh[r * 68 + c4] = a;
        }
        __syncthreads();
    }
    if (r == 0) {
        float4 sv = *(float4*)&red_sh[c4];
        atomicAdd(&g_estats[U_ + c4 + 0], (double)sv.x);
        atomicAdd(&g_estats[U_ + c4 + 1], (double)sv.y);
        atomicAdd(&g_estats[U_ + c4 + 2], (double)sv.z);
        atomicAdd(&g_estats[U_ + c4 + 3], (double)sv.w);
    }
}

// BN scale/shift; reset accumulators.
__global__ void k_finalize(const float* __restrict__ hg, const float* __restrict__ hb,
                           const float* __restrict__ eg, const float* __restrict__ eb) {
    int u = threadIdx.x;  // 64
    double ecnt = (double)E_;
    float emean = (float)(g_estats[u] / ecnt);
    float evar  = (float)(g_estats[U_ + u] / ecnt) - emean * emean;
    float es = eg[u] * rsqrtf(evar + EPS_);
    g_ecoef[u] = es;
    g_ecoef[U_ + u] = eb[u] - emean * es;

    double hcnt = (double)BN_;
    float hmean = (float)(g_hstats[u] / hcnt);
    float hvar  = (float)(g_hstats[U_ + u] / hcnt) - hmean * hmean;
    float hs = hg[u] * rsqrtf(hvar + EPS_);
    g_hcoef[u] = hs;
    g_hcoef[U_ + u] = hb[u] - hmean * hs;

    g_estats[u] = 0.0; g_estats[U_ + u] = 0.0;
    g_hstats[u] = 0.0; g_hstats[U_ + u] = 0.0;
}

// h += lrelu(bn(x1 + pooled))
__global__ void k_happly() {
    int idx = blockIdx.x * 256 + threadIdx.x;
    if (idx >= BN_ * U_) return;
    int u = idx & 63;
    float zh = g_x1[idx] + g_pooled[idx];
    g_h[idx] += lrelu(fmaf(zh, g_hcoef[u], g_hcoef[U_ + u]));
}

// Last layer: residual update fused with final projection.
__global__ void __launch_bounds__(256) k_pass2_last(const float* __restrict__ e1w,
                                                    const float* __restrict__ e1b,
                                                    float* __restrict__ out) {
    __shared__ float sred[4][2];
    int t = threadIdx.x, u = t & 63, g = t >> 6;
    size_t e = (size_t)blockIdx.x * 4 + g;
    size_t o = e * U_ + u;
    float z = g_z[o], w = g_w[o];
    float wn = w + lrelu(fmaf(z, g_ecoef[u], g_ecoef[U_ + u]));
    float v = wn * __ldg(&e1w[u]);
#pragma unroll
    for (int off = 16; off; off >>= 1) v += __shfl_down_sync(0xffffffffu, v, off);
    int warp = t >> 5, lane = t & 31;
    if (lane == 0) sred[warp >> 1][warp & 1] = v;
    __syncthreads();
    if (u == 0) {
        float tot = sred[g][0] + sred[g][1] + __ldg(&e1b[0]);
        int ei = (int)e;
        int b = ei / (N_ * M_);
        int rem = ei - b * (N_ * M_);
        int n = rem / M_;
        int m = rem - n * M_;
        int dst = m + (m >= n);
        out[((size_t)(b * N_ + n)) * N_ + dst] = tot;
    }
}

__global__ void k_zdiag(float* __restrict__ out) {
    int idx = blockIdx.x * 256 + threadIdx.x;
    if (idx >= BN_) return;
    int b = idx / N_, n = idx % N_;
    out[((size_t)(b * N_ + n)) * N_ + n] = 0.f;
}

extern "C" void kernel_launch(void* const* d_in, const int* in_sizes, int n_in,
                              void* d_out, int out_size) {
    const float* x    = (const float*)d_in[0];
    const float* adj  = (const float*)d_in[1];
    const float* vl0w = (const float*)d_in[2];
    const float* vl0b = (const float*)d_in[3];
    const float* vw1  = (const float*)d_in[4];
    const float* vb1  = (const float*)d_in[5];
    const float* vw2  = (const float*)d_in[6];
    const float* vb2  = (const float*)d_in[7];
    const float* vw3  = (const float*)d_in[8];
    const float* vb3  = (const float*)d_in[9];
    const float* vw4  = (const float*)d_in[10];
    const float* vb4  = (const float*)d_in[11];
    const float* vbng = (const float*)d_in[12];
    const float* vbnb = (const float*)d_in[13];
    const float* el0w = (const float*)d_in[14];
    const float* el0b = (const float*)d_in[15];
    const float* ew   = (const float*)d_in[16];
    const float* eb   = (const float*)d_in[17];
    const float* ebng = (const float*)d_in[18];
    const float* ebnb = (const float*)d_in[19];
    const float* e1w  = (const float*)d_in[20];
    const float* e1b  = (const float*)d_in[21];
    float* out = (float*)d_out;

    k_init_h<<<(BN_ * U_ + 255) / 256, 256>>>(x, vl0w, vl0b);
    k_init_w<<<dim3(50, N_, B_), 256>>>(adj, el0w, el0b);

    for (int i = 0; i < L_; i++) {
        k_xs<<<BN_, 256>>>(vw1 + i * U_ * U_, vb1 + i * U_,
                           vw2 + i * U_ * U_, vb2 + i * U_,
                           vw3 + i * U_ * U_, vb3 + i * U_,
                           vw4 + i * U_ * U_, vb4 + i * U_);
        k_pass1<<<BN_, 256>>>(ew + i * U_ * U_, eb + i * U_, i > 0 ? 1 : 0);
        k_finalize<<<1, 64>>>(vbng + i * U_, vbnb + i * U_, ebng + i * U_, ebnb + i * U_);
        if (i < L_ - 1) k_happly<<<(BN_ * U_ + 255) / 256, 256>>>();
    }
    k_pass2_last<<<(int)(E_ / 4), 256>>>(e1w, e1b, out);
    k_zdiag<<<(BN_ + 255) / 256, 256>>>(out);
}